// round 7
// baseline (speedup 1.0000x reference)
#include <cuda_runtime.h>
#include <math.h>

#define BB 64
#define SS 512
#define HH 768
#define LL 9

// scratch (no allocations allowed in kernel_launch)
__device__ int   g_src[BB * SS];     // g_src[b*SS + p] = source token s for compacted slot p
__device__ int   g_cnt[BB];          // valid tokens per row
__device__ int   g_rowoff[BB + 1];   // exclusive prefix of g_cnt; g_rowoff[64] = total
__device__ float g_Wt[LL * HH];      // W transposed: g_Wt[j*HH + k] = W[k*LL + j]

// ---------------------------------------------------------------------------
// Kernel 1: ballot-based per-row scan of valid_mask -> gather idx + counts.
// Also transposes W into g_Wt (spread across the 64 blocks).
// ---------------------------------------------------------------------------
__global__ void __launch_bounds__(SS) ner_scan_kernel(const int* __restrict__ mask,
                                                      const float* __restrict__ W) {
    __shared__ int wsum[16];
    const int b = blockIdx.x;
    const int s = threadIdx.x;
    const int lane = s & 31;
    const int wid  = s >> 5;
    const int m = mask[b * SS + s];
    const unsigned bal = __ballot_sync(0xffffffffu, m != 0);
    const int pre = __popc(bal & ((1u << lane) - 1u));
    if (lane == 31) wsum[wid] = __popc(bal);

    // transpose a 108-element slice of W (64 blocks x 108 = 6912 = LL*HH)
    {
        const int idx = b * 108 + s;
        if (s < 108) {
            const int k = idx / LL;
            const int j = idx - k * LL;
            g_Wt[j * HH + k] = W[idx];
        }
    }

    __syncthreads();
    if (wid == 0 && lane < 16) {
        int v = wsum[lane];
#pragma unroll
        for (int off = 1; off < 16; off <<= 1) {
            int u = __shfl_up_sync(0xffffu, v, off);
            if (lane >= off) v += u;
        }
        wsum[lane] = v;
    }
    __syncthreads();
    const int offset = wid ? wsum[wid - 1] : 0;
    if (m) g_src[b * SS + offset + pre] = s;
    if (s == SS - 1) g_cnt[b] = offset + pre + (m ? 1 : 0);
}

// ---------------------------------------------------------------------------
// Kernel 2: fill ENTIRE output with softmax(bias) (valid slots get
// overwritten by kernel 3). Block 0 additionally computes g_rowoff.
// Grid: 294912 floats / 4 / 256 = 288 blocks.
// ---------------------------------------------------------------------------
__global__ void __launch_bounds__(256) ner_fill_kernel(const float* __restrict__ bias,
                                                       float* __restrict__ out) {
    const int tid = threadIdx.x;

    if (blockIdx.x == 0) {            // prefix over the 64 row counts
        __shared__ int sh[BB];
        if (tid < BB) sh[tid] = g_cnt[tid];
        __syncthreads();
        for (int off = 1; off < BB; off <<= 1) {
            int v = (tid >= off && tid < BB) ? sh[tid - off] : 0;
            __syncthreads();
            if (tid < BB) sh[tid] += v;
            __syncthreads();
        }
        if (tid < BB) g_rowoff[tid + 1] = sh[tid];
        if (tid == 0) g_rowoff[0] = 0;
    }

    __shared__ float ssb[LL];
    if (tid == 0) {
        float t[LL];
        float mx = -1e30f;
#pragma unroll
        for (int j = 0; j < LL; j++) { t[j] = __ldg(bias + j); mx = fmaxf(mx, t[j]); }
        float sum = 0.f;
#pragma unroll
        for (int j = 0; j < LL; j++) { t[j] = __expf(t[j] - mx); sum += t[j]; }
        const float inv = 1.f / sum;
#pragma unroll
        for (int j = 0; j < LL; j++) ssb[j] = t[j] * inv;
    }
    __syncthreads();

    const int idx = blockIdx.x * 256 + tid;            // float4 index
    if (idx < (BB * SS * LL) / 4) {
        const int base = (idx * 4) % LL;
        float4 v;
        v.x = ssb[base];
        v.y = ssb[(base + 1) % LL];
        v.z = ssb[(base + 2) % LL];
        v.w = ssb[(base + 3) % LL];
        ((float4*)out)[idx] = v;
    }
}

// ---------------------------------------------------------------------------
// Kernel 3: dense over VALID tokens only. 256-thr blocks, 8 warps,
// 2 tokens/warp, grid-stride over 16-token chunks. No shared memory:
// W via __ldg (L1-resident, shared across blocks on the SM), X via __ldcg
// (streams through L2, does not evict W from L1).
// ---------------------------------------------------------------------------
__global__ void __launch_bounds__(256) ner_main_kernel(const float* __restrict__ X,
                                                       const float* __restrict__ bias,
                                                       float* __restrict__ out) {
    const int tid  = threadIdx.x;
    const int lane = tid & 31;
    const int warp = tid >> 5;
    const int total = g_rowoff[BB];
    const float4* Wt4 = (const float4*)g_Wt;          // [LL][192] float4

    for (int chunk = blockIdx.x; chunk * 16 < total; chunk += gridDim.x) {
        const int base = chunk * 16 + warp * 2;        // this warp's first dense token
        if (base >= total) continue;
        const int nv = min(2, total - base);

        // lanes 0..1 locate their token: dense d -> (row, p) -> src, dst
        int srcg = 0, dstg = 0;
        if (lane < 2) {
            const int d = base + ((lane < nv) ? lane : 0);
            int r = 0;
#pragma unroll
            for (int st = 32; st >= 1; st >>= 1)
                if (g_rowoff[r + st] <= d) r += st;
            const int p = d - g_rowoff[r];
            srcg = r * SS + g_src[r * SS + p];
            dstg = r * SS + p;
        }
        const int s0 = __shfl_sync(0xffffffffu, srcg, 0);
        const int s1 = __shfl_sync(0xffffffffu, srcg, 1);
        const int d0 = __shfl_sync(0xffffffffu, dstg, 0);
        const int d1 = __shfl_sync(0xffffffffu, dstg, 1);

        const float4* xp0 = (const float4*)(X + (size_t)s0 * HH);
        const float4* xp1 = (const float4*)(X + (size_t)s1 * HH);
        float4 c0 = __ldcg(xp0 + lane);
        float4 c1 = __ldcg(xp1 + lane);

        float a0[LL], a1[LL];
#pragma unroll
        for (int j = 0; j < LL; j++) { a0[j] = 0.f; a1[j] = 0.f; }

#pragma unroll
        for (int it = 0; it < HH / 128; it++) {        // 6 iterations
            const int k4 = it * 32 + lane;
            float4 n0, n1;
            if (it < HH / 128 - 1) {                   // prefetch next iteration
                n0 = __ldcg(xp0 + k4 + 32);
                n1 = __ldcg(xp1 + k4 + 32);
            }
#pragma unroll
            for (int j = 0; j < LL; j++) {
                const float4 w = __ldg(Wt4 + j * (HH / 4) + k4);
                a0[j] += c0.x * w.x + c0.y * w.y + c0.z * w.z + c0.w * w.w;
                a1[j] += c1.x * w.x + c1.y * w.y + c1.z * w.z + c1.w * w.w;
            }
            if (it < HH / 128 - 1) { c0 = n0; c1 = n1; }
        }

#pragma unroll
        for (int j = 0; j < LL; j++) {
            float u = a0[j], v = a1[j];
            u += __shfl_xor_sync(0xffffffffu, u, 16);
            u += __shfl_xor_sync(0xffffffffu, u, 8);
            u += __shfl_xor_sync(0xffffffffu, u, 4);
            u += __shfl_xor_sync(0xffffffffu, u, 2);
            u += __shfl_xor_sync(0xffffffffu, u, 1);
            v += __shfl_xor_sync(0xffffffffu, v, 16);
            v += __shfl_xor_sync(0xffffffffu, v, 8);
            v += __shfl_xor_sync(0xffffffffu, v, 4);
            v += __shfl_xor_sync(0xffffffffu, v, 2);
            v += __shfl_xor_sync(0xffffffffu, v, 1);
            a0[j] = u;
            a1[j] = v;
        }

        {   // token 0 (always valid when we got here)
            float mx = -1e30f;
#pragma unroll
            for (int j = 0; j < LL; j++) { a0[j] += __ldg(bias + j); mx = fmaxf(mx, a0[j]); }
            float sum = 0.f;
#pragma unroll
            for (int j = 0; j < LL; j++) { a0[j] = __expf(a0[j] - mx); sum += a0[j]; }
            const float inv = 1.f / sum;
            if (lane < LL) out[(size_t)d0 * LL + lane] = a0[lane] * inv;
        }
        if (nv > 1) {
            float mx = -1e30f;
#pragma unroll
            for (int j = 0; j < LL; j++) { a1[j] += __ldg(bias + j); mx = fmaxf(mx, a1[j]); }
            float sum = 0.f;
#pragma unroll
            for (int j = 0; j < LL; j++) { a1[j] = __expf(a1[j] - mx); sum += a1[j]; }
            const float inv = 1.f / sum;
            if (lane < LL) out[(size_t)d1 * LL + lane] = a1[lane] * inv;
        }
    }
}

// ---------------------------------------------------------------------------
extern "C" void kernel_launch(void* const* d_in, const int* in_sizes, int n_in,
                              void* d_out, int out_size) {
    const float* seq  = nullptr;  // [64,512,768] f32
    const int*   mask = nullptr;  // [64,512]     i32
    const float* W    = nullptr;  // [768,9]      f32
    const float* bias = nullptr;  // [9]          f32
    for (int i = 0; i < n_in; i++) {
        switch (in_sizes[i]) {
            case BB * SS * HH: seq  = (const float*)d_in[i]; break;
            case BB * SS:      mask = (const int*)d_in[i];   break;
            case HH * LL:      W    = (const float*)d_in[i]; break;
            case LL:           bias = (const float*)d_in[i]; break;
        }
    }
    float* out = (float*)d_out;

    ner_scan_kernel<<<BB, SS>>>(mask, W);
    ner_fill_kernel<<<(BB * SS * LL) / 4 / 256, 256>>>(bias, out);   // 288 blocks
    ner_main_kernel<<<148 * 8, 256>>>(seq, bias, out);               // 1184 blocks
}

// round 11
// speedup vs baseline: 1.4070x; 1.4070x over previous
#include <cuda_runtime.h>
#include <math.h>

#define BB 64
#define SS 512
#define HH 768
#define LL 9

// scratch (no allocations allowed in kernel_launch)
__device__ int   g_src[BB * SS];     // g_src[b*SS + p] = source token s for compacted slot p
__device__ int   g_cnt[BB];          // valid tokens per row
__device__ int   g_rowoff[BB + 1];   // exclusive prefix of g_cnt; g_rowoff[64] = total
__device__ float g_Wt[LL * HH];      // W transposed: g_Wt[j*HH + k] = W[k*LL + j]

// ---------------------------------------------------------------------------
// Kernel 1: ballot-based per-row scan of valid_mask -> gather idx + counts.
// Also transposes W into g_Wt (spread across the 64 blocks).
// ---------------------------------------------------------------------------
__global__ void __launch_bounds__(SS) ner_scan_kernel(const int* __restrict__ mask,
                                                      const float* __restrict__ W) {
    __shared__ int wsum[16];
    const int b    = blockIdx.x;
    const int s    = threadIdx.x;
    const int lane = s & 31;
    const int wid  = s >> 5;
    const int m    = mask[b * SS + s];
    const unsigned bal = __ballot_sync(0xffffffffu, m != 0);
    const int pre  = __popc(bal & ((1u << lane) - 1u));
    if (lane == 31) wsum[wid] = __popc(bal);

    // transpose a 108-element slice of W (64 blocks x 108 = 6912 = LL*HH)
    if (s < 108) {
        const int idx = b * 108 + s;
        const int k = idx / LL;
        const int j = idx - k * LL;
        g_Wt[j * HH + k] = W[idx];
    }

    __syncthreads();
    if (wid == 0 && lane < 16) {
        int v = wsum[lane];
#pragma unroll
        for (int off = 1; off < 16; off <<= 1) {
            int u = __shfl_up_sync(0xffffu, v, off);
            if (lane >= off) v += u;
        }
        wsum[lane] = v;
    }
    __syncthreads();
    const int offset = wid ? wsum[wid - 1] : 0;
    if (m) g_src[b * SS + offset + pre] = s;
    if (s == SS - 1) g_cnt[b] = offset + pre + (m ? 1 : 0);
}

// ---------------------------------------------------------------------------
// Kernel 2: block b writes softmax(bias) into the TAIL slots of row b
// (p in [cnt, 512)). Block 0 also computes the g_rowoff prefix.
// Disjoint from the slots the main kernel writes.
// ---------------------------------------------------------------------------
__global__ void __launch_bounds__(256) ner_fill_kernel(const float* __restrict__ bias,
                                                       float* __restrict__ out) {
    const int tid = threadIdx.x;
    const int b   = blockIdx.x;

    if (b == 0) {                     // prefix over the 64 row counts
        __shared__ int sh[BB];
        if (tid < BB) sh[tid] = g_cnt[tid];
        __syncthreads();
        for (int off = 1; off < BB; off <<= 1) {
            int v = (tid >= off && tid < BB) ? sh[tid - off] : 0;
            __syncthreads();
            if (tid < BB) sh[tid] += v;
            __syncthreads();
        }
        if (tid < BB) g_rowoff[tid + 1] = sh[tid];
        if (tid == 0) g_rowoff[0] = 0;
    }

    __shared__ float ssb[LL];
    if (tid == 0) {
        float t[LL];
        float mx = -1e30f;
#pragma unroll
        for (int j = 0; j < LL; j++) { t[j] = bias[j]; mx = fmaxf(mx, t[j]); }
        float sum = 0.f;
#pragma unroll
        for (int j = 0; j < LL; j++) { t[j] = __expf(t[j] - mx); sum += t[j]; }
        const float inv = 1.f / sum;
#pragma unroll
        for (int j = 0; j < LL; j++) ssb[j] = t[j] * inv;
    }
    __syncthreads();

    const int cnt = g_cnt[b];
    float* base = out + ((size_t)b * SS + cnt) * LL;   // multiple-of-9 float offset
    const int n = (SS - cnt) * LL;
    for (int i = tid; i < n; i += 256) base[i] = ssb[i % LL];
}

// ---------------------------------------------------------------------------
// Kernel 3: dense over VALID tokens. 256-thr blocks, 8 warps, 2 tokens/warp,
// grid-stride over 16-token chunks. W in smem (cheap float4 copy of the
// pre-transposed g_Wt). __launch_bounds__(256,4) caps regs at 64 ->
// 4 blocks/SM = 32 warps/SM.
// ---------------------------------------------------------------------------
__global__ void __launch_bounds__(256, 4) ner_main_kernel(const float* __restrict__ X,
                                                          const float* __restrict__ bias,
                                                          float* __restrict__ out) {
    const int tid   = threadIdx.x;
    const int lane  = tid & 31;
    const int warp  = tid >> 5;
    const int total = g_rowoff[BB];

    if (blockIdx.x * 16 >= total) return;      // no chunk for this block (uniform)

    __shared__ float sWt[LL * HH];
    {
        const float4* src = (const float4*)g_Wt;
        float4* dst = (float4*)sWt;
        for (int i = tid; i < (LL * HH) / 4; i += 256) dst[i] = src[i];
    }
    __syncthreads();

    // cache bias once (registers, reused across all chunks)
    float bb[LL];
#pragma unroll
    for (int j = 0; j < LL; j++) bb[j] = bias[j];

    for (int chunk = blockIdx.x; chunk * 16 < total; chunk += gridDim.x) {
        const int base = chunk * 16 + warp * 2;
        if (base >= total) continue;
        const int nv = min(2, total - base);

        // lanes 0..1 locate their dense token: d -> (row, p) -> src, dst
        int srcg = 0, dstg = 0;
        if (lane < 2) {
            const int d = base + ((lane < nv) ? lane : 0);
            int r = 0;
#pragma unroll
            for (int st = 32; st >= 1; st >>= 1)
                if (g_rowoff[r + st] <= d) r += st;
            const int p = d - g_rowoff[r];
            srcg = r * SS + g_src[r * SS + p];
            dstg = r * SS + p;
        }
        const int s0 = __shfl_sync(0xffffffffu, srcg, 0);
        const int s1 = __shfl_sync(0xffffffffu, srcg, 1);
        const int d0 = __shfl_sync(0xffffffffu, dstg, 0);
        const int d1 = __shfl_sync(0xffffffffu, dstg, 1);

        const float4* xp0 = (const float4*)(X + (size_t)s0 * HH);
        const float4* xp1 = (const float4*)(X + (size_t)s1 * HH);
        float4 c0 = xp0[lane];
        float4 c1 = xp1[lane];

        float a0[LL], a1[LL];
#pragma unroll
        for (int j = 0; j < LL; j++) { a0[j] = 0.f; a1[j] = 0.f; }

#pragma unroll
        for (int it = 0; it < HH / 128; it++) {        // 6 iterations
            const int k4 = it * 32 + lane;
            float4 n0, n1;
            if (it < HH / 128 - 1) {                   // prefetch next iteration
                n0 = xp0[k4 + 32];
                n1 = xp1[k4 + 32];
            }
#pragma unroll
            for (int j = 0; j < LL; j++) {
                const float4 w = *(const float4*)(sWt + j * HH + k4 * 4);
                a0[j] += c0.x * w.x + c0.y * w.y + c0.z * w.z + c0.w * w.w;
                a1[j] += c1.x * w.x + c1.y * w.y + c1.z * w.z + c1.w * w.w;
            }
            if (it < HH / 128 - 1) { c0 = n0; c1 = n1; }
        }

#pragma unroll
        for (int j = 0; j < LL; j++) {
            float u = a0[j], v = a1[j];
            u += __shfl_xor_sync(0xffffffffu, u, 16);
            u += __shfl_xor_sync(0xffffffffu, u, 8);
            u += __shfl_xor_sync(0xffffffffu, u, 4);
            u += __shfl_xor_sync(0xffffffffu, u, 2);
            u += __shfl_xor_sync(0xffffffffu, u, 1);
            v += __shfl_xor_sync(0xffffffffu, v, 16);
            v += __shfl_xor_sync(0xffffffffu, v, 8);
            v += __shfl_xor_sync(0xffffffffu, v, 4);
            v += __shfl_xor_sync(0xffffffffu, v, 2);
            v += __shfl_xor_sync(0xffffffffu, v, 1);
            a0[j] = u;
            a1[j] = v;
        }

        {   // token 0 (always valid here)
            float mx = -1e30f;
#pragma unroll
            for (int j = 0; j < LL; j++) { a0[j] += bb[j]; mx = fmaxf(mx, a0[j]); }
            float sum = 0.f;
#pragma unroll
            for (int j = 0; j < LL; j++) { a0[j] = __expf(a0[j] - mx); sum += a0[j]; }
            const float inv = 1.f / sum;
            if (lane < LL) out[(size_t)d0 * LL + lane] = a0[lane] * inv;
        }
        if (nv > 1) {
            float mx = -1e30f;
#pragma unroll
            for (int j = 0; j < LL; j++) { a1[j] += bb[j]; mx = fmaxf(mx, a1[j]); }
            float sum = 0.f;
#pragma unroll
            for (int j = 0; j < LL; j++) { a1[j] = __expf(a1[j] - mx); sum += a1[j]; }
            const float inv = 1.f / sum;
            if (lane < LL) out[(size_t)d1 * LL + lane] = a1[lane] * inv;
        }
    }
}

// ---------------------------------------------------------------------------
extern "C" void kernel_launch(void* const* d_in, const int* in_sizes, int n_in,
                              void* d_out, int out_size) {
    const float* seq  = nullptr;  // [64,512,768] f32
    const int*   mask = nullptr;  // [64,512]     i32
    const float* W    = nullptr;  // [768,9]      f32
    const float* bias = nullptr;  // [9]          f32
    for (int i = 0; i < n_in; i++) {
        switch (in_sizes[i]) {
            case BB * SS * HH: seq  = (const float*)d_in[i]; break;
            case BB * SS:      mask = (const int*)d_in[i];   break;
            case HH * LL:      W    = (const float*)d_in[i]; break;
            case LL:           bias = (const float*)d_in[i]; break;
        }
    }
    float* out = (float*)d_out;

    ner_scan_kernel<<<BB, SS>>>(mask, W);
    ner_fill_kernel<<<BB, 256>>>(bias, out);            // tail slots + prefix
    ner_main_kernel<<<148 * 8, 256>>>(seq, bias, out);  // 1184 blocks, grid-stride
}

// round 12
// speedup vs baseline: 1.6547x; 1.1761x over previous
#include <cuda_runtime.h>
#include <math.h>

#define BB 64
#define SS 512
#define HH 768
#define LL 9

// scratch (no allocations allowed in kernel_launch)
__device__ int   g_src[BB * SS];   // g_src[b*SS + p] = source token s for compacted slot p
__device__ int   g_cnt[BB];        // valid tokens per row
__device__ float g_Wt[LL * HH];    // W transposed: g_Wt[j*HH + k] = W[k*LL + j]

// ---------------------------------------------------------------------------
// Kernel 1: per-row ballot scan -> gather idx + count; transposes a slice of
// W into g_Wt; writes softmax(bias) into this row's TAIL slots [cnt, 512).
// ---------------------------------------------------------------------------
__global__ void __launch_bounds__(SS) ner_scan_kernel(const int* __restrict__ mask,
                                                      const float* __restrict__ W,
                                                      const float* __restrict__ bias,
                                                      float* __restrict__ out) {
    __shared__ int wsum[16];
    const int b    = blockIdx.x;
    const int s    = threadIdx.x;
    const int lane = s & 31;
    const int wid  = s >> 5;
    const int m    = mask[b * SS + s];
    const unsigned bal = __ballot_sync(0xffffffffu, m != 0);
    const int pre  = __popc(bal & ((1u << lane) - 1u));
    if (lane == 31) wsum[wid] = __popc(bal);

    // transpose a 108-element slice of W (64 blocks x 108 = 6912 = LL*HH)
    if (s < 108) {
        const int idx = b * 108 + s;
        const int k = idx / LL;
        const int j = idx - k * LL;
        g_Wt[j * HH + k] = W[idx];
    }

    __syncthreads();
    if (wid == 0 && lane < 16) {
        int v = wsum[lane];
#pragma unroll
        for (int off = 1; off < 16; off <<= 1) {
            int u = __shfl_up_sync(0xffffu, v, off);
            if (lane >= off) v += u;
        }
        wsum[lane] = v;   // inclusive scan of warp sums
    }
    __syncthreads();
    const int offset = wid ? wsum[wid - 1] : 0;
    if (m) g_src[b * SS + offset + pre] = s;
    const int cnt = wsum[15];
    if (s == 0) g_cnt[b] = cnt;

    // softmax(bias) in registers (all threads, redundant & cheap)
    float t[LL];
    float mx = -1e30f;
#pragma unroll
    for (int j = 0; j < LL; j++) { t[j] = bias[j]; mx = fmaxf(mx, t[j]); }
    float sum = 0.f;
#pragma unroll
    for (int j = 0; j < LL; j++) { t[j] = __expf(t[j] - mx); sum += t[j]; }
    const float inv = 1.f / sum;
#pragma unroll
    for (int j = 0; j < LL; j++) t[j] *= inv;

    // tail fill for this row: slots [cnt, 512)
    float* base = out + ((size_t)b * SS + cnt) * LL;   // multiple-of-9 offset
    const int n = (SS - cnt) * LL;
    for (int i = s; i < n; i += SS) base[i] = t[i % LL];
}

// ---------------------------------------------------------------------------
// Kernel 2: static mapping, 32 slots/block (one row), 8 warps x 4 tokens.
// Dead blocks/warps return immediately (tails already written by kernel 1).
// 3-phase deep load batching: two 8-load register buffers keep up to 16
// LDG.128 outstanding per warp (8 KB/warp in flight).
// ---------------------------------------------------------------------------
__global__ void __launch_bounds__(256, 2) ner_main_kernel(const float* __restrict__ X,
                                                          const float* __restrict__ bias,
                                                          float* __restrict__ out) {
    const int tid  = threadIdx.x;
    const int lane = tid & 31;
    const int tb   = blockIdx.x * 32;
    const int bi   = tb >> 9;            // SS = 512
    const int pb   = tb & (SS - 1);
    const int cnt  = g_cnt[bi];

    if (pb >= cnt) return;               // whole block is tail (block-uniform)

    __shared__ float sWt[LL * HH];
    __shared__ float sB[LL];
    {
        const float4* src = (const float4*)g_Wt;
        float4* dst = (float4*)sWt;
        for (int i = tid; i < (LL * HH) / 4; i += 256) dst[i] = src[i];
        if (tid < LL) sB[tid] = bias[tid];
    }
    __syncthreads();

    const int warp = tid >> 5;
    const int t0   = tb + warp * 4;
    const int p0   = t0 & (SS - 1);
    if (p0 >= cnt) return;               // tail warp: already written by kernel 1

    const int nv = min(4, cnt - p0);
    const float4* xp[4];
#pragma unroll
    for (int i = 0; i < 4; i++) {
        const int pi = p0 + ((i < nv) ? i : 0);   // clamp (write suppressed later)
        xp[i] = (const float4*)(X + ((size_t)bi * SS + g_src[bi * SS + pi]) * HH);
    }

    // Phase buffers: A holds iters {0,1} then {4,5}; Bf holds iters {2,3}.
    float4 A[4][2], Bf[4][2];
#pragma unroll
    for (int i = 0; i < 4; i++) {        // 8 loads: iters 0,1
        A[i][0] = xp[i][lane];
        A[i][1] = xp[i][32 + lane];
    }
#pragma unroll
    for (int i = 0; i < 4; i++) {        // 8 more loads in flight: iters 2,3
        Bf[i][0] = xp[i][64 + lane];
        Bf[i][1] = xp[i][96 + lane];
    }

    float acc[4][LL];
#pragma unroll
    for (int i = 0; i < 4; i++)
#pragma unroll
        for (int j = 0; j < LL; j++) acc[i][j] = 0.f;

    // FMA iters 0,1 (consumes A)
#pragma unroll
    for (int h = 0; h < 2; h++) {
        const int k4 = h * 32 + lane;
#pragma unroll
        for (int j = 0; j < LL; j++) {
            const float4 w = *(const float4*)(sWt + j * HH + k4 * 4);
#pragma unroll
            for (int i = 0; i < 4; i++)
                acc[i][j] += A[i][h].x * w.x + A[i][h].y * w.y +
                             A[i][h].z * w.z + A[i][h].w * w.w;
        }
    }
    // reload A with iters 4,5 (issued before consuming Bf)
#pragma unroll
    for (int i = 0; i < 4; i++) {
        A[i][0] = xp[i][128 + lane];
        A[i][1] = xp[i][160 + lane];
    }
    // FMA iters 2,3 (consumes Bf)
#pragma unroll
    for (int h = 0; h < 2; h++) {
        const int k4 = (2 + h) * 32 + lane;
#pragma unroll
        for (int j = 0; j < LL; j++) {
            const float4 w = *(const float4*)(sWt + j * HH + k4 * 4);
#pragma unroll
            for (int i = 0; i < 4; i++)
                acc[i][j] += Bf[i][h].x * w.x + Bf[i][h].y * w.y +
                             Bf[i][h].z * w.z + Bf[i][h].w * w.w;
        }
    }
    // FMA iters 4,5 (consumes reloaded A)
#pragma unroll
    for (int h = 0; h < 2; h++) {
        const int k4 = (4 + h) * 32 + lane;
#pragma unroll
        for (int j = 0; j < LL; j++) {
            const float4 w = *(const float4*)(sWt + j * HH + k4 * 4);
#pragma unroll
            for (int i = 0; i < 4; i++)
                acc[i][j] += A[i][h].x * w.x + A[i][h].y * w.y +
                             A[i][h].z * w.z + A[i][h].w * w.w;
        }
    }

    // warp reduction: every lane ends with the full sums
#pragma unroll
    for (int i = 0; i < 4; i++)
#pragma unroll
        for (int j = 0; j < LL; j++) {
            float u = acc[i][j];
            u += __shfl_xor_sync(0xffffffffu, u, 16);
            u += __shfl_xor_sync(0xffffffffu, u, 8);
            u += __shfl_xor_sync(0xffffffffu, u, 4);
            u += __shfl_xor_sync(0xffffffffu, u, 2);
            u += __shfl_xor_sync(0xffffffffu, u, 1);
            acc[i][j] = u;
        }

#pragma unroll
    for (int i = 0; i < 4; i++) {
        if (i < nv) {
            float l[LL];
            float mx = -1e30f;
#pragma unroll
            for (int j = 0; j < LL; j++) { l[j] = acc[i][j] + sB[j]; mx = fmaxf(mx, l[j]); }
            float sum = 0.f;
#pragma unroll
            for (int j = 0; j < LL; j++) { l[j] = __expf(l[j] - mx); sum += l[j]; }
            const float inv = 1.f / sum;
            if (lane < LL) out[(size_t)(t0 + i) * LL + lane] = l[lane] * inv;
        }
    }
}

// ---------------------------------------------------------------------------
extern "C" void kernel_launch(void* const* d_in, const int* in_sizes, int n_in,
                              void* d_out, int out_size) {
    const float* seq  = nullptr;  // [64,512,768] f32
    const int*   mask = nullptr;  // [64,512]     i32
    const float* W    = nullptr;  // [768,9]      f32
    const float* bias = nullptr;  // [9]          f32
    for (int i = 0; i < n_in; i++) {
        switch (in_sizes[i]) {
            case BB * SS * HH: seq  = (const float*)d_in[i]; break;
            case BB * SS:      mask = (const int*)d_in[i];   break;
            case HH * LL:      W    = (const float*)d_in[i]; break;
            case LL:           bias = (const float*)d_in[i]; break;
        }
    }
    float* out = (float*)d_out;

    ner_scan_kernel<<<BB, SS>>>(mask, W, bias, out);       // scan + W^T + tail fill
    ner_main_kernel<<<(BB * SS) / 32, 256>>>(seq, bias, out);  // 1024 blocks
}